// round 1
// baseline (speedup 1.0000x reference)
#include <cuda_runtime.h>
#include <cstdint>

// ---------------- problem constants ----------------
#define BB 8
#define NN 2048
#define KNBR 20
#define NPTS (BB*NN)          // 16384
#define EDGE_CNT (NPTS*KNBR)  // 327680

// ---------------- device scratch (static, no runtime alloc) ----------------
__device__ float g_D[(size_t)BB*NN*NN];        // 134 MB pairwise neg-dist
__device__ int   g_idx[NPTS*KNBR];             // global neighbor ids
__device__ float g_xx[NPTS];                   // squared norms
__device__ float g_uv[(size_t)NPTS*512];       // [n][2O]: u | v
__device__ float g_Wt[512*128];                // [2O][C]: (W1-W2) | W2
__device__ float g_xa[(size_t)NPTS*64];        // layer1 out
__device__ float g_xb[(size_t)NPTS*128];       // layer2 out
__device__ float g_xc[(size_t)NPTS*256];       // layer3 out
__device__ float g_psum[512*256];
__device__ float g_psq [512*256];
__device__ float g_scale[256];
__device__ float g_shift[256];
__device__ float g_pool[BB*256];

// ---------------- squared norms ----------------
__global__ void xx_kernel(const float* __restrict__ x, float* __restrict__ xx, int C)
{
    int n = blockIdx.x * 256 + threadIdx.x;
    if (n >= NPTS) return;
    const float* p = x + (size_t)n * C;
    float s = 0.f;
    for (int c = 0; c < C; ++c) s = fmaf(p[c], p[c], s);
    xx[n] = s;
}

// ---------------- generic fp32 GEMM-NT: C[M][Nn] = A[M][K] * B[Nn][K]^T ----------------
// MODE 0: plain, + bias[c] for c < Obias (u|v computation)
// MODE 1: dist epilogue: 2*acc - xx[r] - xx[c]
#define BM 128
#define BN 128
#define BKK 16

template<int MODE>
__global__ void gemm_nt(const float* __restrict__ A, const float* __restrict__ Bm,
                        float* __restrict__ Cout, int M, int Nn, int K,
                        long long strideA, long long strideB, long long strideC,
                        const float* __restrict__ xx, long long strideXX,
                        const float* __restrict__ bias, int Obias)
{
    const float* Ab = A  + blockIdx.z * strideA;
    const float* Bb = Bm + blockIdx.z * strideB;
    float*       Cb = Cout + blockIdx.z * strideC;
    const float* xxb = (MODE == 1) ? (xx + blockIdx.z * strideXX) : nullptr;

    __shared__ float As[BKK][BM + 4];
    __shared__ float Bs[BKK][BN + 4];

    int tid = threadIdx.x;
    int tx = tid & 15, ty = tid >> 4;
    int tx4 = tx * 4, ty4 = ty * 4;
    int rowBase = blockIdx.y * BM;
    int colBase = blockIdx.x * BN;

    float acc[8][8];
#pragma unroll
    for (int i = 0; i < 8; ++i)
#pragma unroll
        for (int j = 0; j < 8; ++j) acc[i][j] = 0.f;

    for (int k0 = 0; k0 < K; k0 += BKK) {
#pragma unroll
        for (int i = 0; i < 8; ++i) {
            int idx = tid + i * 256;
            int kk = idx & 15, r = idx >> 4;
            int gk = k0 + kk;
            As[kk][r] = (gk < K) ? Ab[(size_t)(rowBase + r) * K + gk] : 0.f;
        }
#pragma unroll
        for (int i = 0; i < 8; ++i) {
            int idx = tid + i * 256;
            int kk = idx & 15, r = idx >> 4;
            int gk = k0 + kk;
            Bs[kk][r] = (gk < K) ? Bb[(size_t)(colBase + r) * K + gk] : 0.f;
        }
        __syncthreads();

#pragma unroll
        for (int kk = 0; kk < BKK; ++kk) {
            float4 a0 = *reinterpret_cast<const float4*>(&As[kk][ty4]);
            float4 a1 = *reinterpret_cast<const float4*>(&As[kk][ty4 + 64]);
            float4 b0 = *reinterpret_cast<const float4*>(&Bs[kk][tx4]);
            float4 b1 = *reinterpret_cast<const float4*>(&Bs[kk][tx4 + 64]);
            float av[8] = {a0.x, a0.y, a0.z, a0.w, a1.x, a1.y, a1.z, a1.w};
            float bv[8] = {b0.x, b0.y, b0.z, b0.w, b1.x, b1.y, b1.z, b1.w};
#pragma unroll
            for (int i = 0; i < 8; ++i)
#pragma unroll
                for (int j = 0; j < 8; ++j)
                    acc[i][j] = fmaf(av[i], bv[j], acc[i][j]);
        }
        __syncthreads();
    }

    // epilogue
    float colv[8];
#pragma unroll
    for (int j = 0; j < 8; ++j) {
        int c = colBase + ((j < 4) ? tx4 + j : tx4 + j + 60);
        if (MODE == 1)       colv[j] = xxb[c];
        else                 colv[j] = (c < Obias) ? bias[c] : 0.f;
    }
#pragma unroll
    for (int i = 0; i < 8; ++i) {
        int r = rowBase + ((i < 4) ? ty4 + i : ty4 + i + 60);
        float xr = (MODE == 1) ? xxb[r] : 0.f;
        float out[8];
#pragma unroll
        for (int j = 0; j < 8; ++j) {
            if (MODE == 1) out[j] = 2.f * acc[i][j] - xr - colv[j];
            else           out[j] = acc[i][j] + colv[j];
        }
        float4 v0 = make_float4(out[0], out[1], out[2], out[3]);
        float4 v1 = make_float4(out[4], out[5], out[6], out[7]);
        *reinterpret_cast<float4*>(&Cb[(size_t)r * Nn + colBase + tx4])      = v0;
        *reinterpret_cast<float4*>(&Cb[(size_t)r * Nn + colBase + tx4 + 64]) = v1;
    }
}

// ---------------- top-k (largest neg_dist) per query ----------------
__global__ void topk_kernel(const float* __restrict__ D, int* __restrict__ out)
{
    __shared__ float vals[NN];
    __shared__ float wv[8];
    __shared__ int   wi[8];

    int q = blockIdx.x;                    // global point id
    const float* row = D + (size_t)q * NN;
    int tid = threadIdx.x;

    for (int i = tid; i < NN; i += 256) vals[i] = row[i];
    __syncthreads();

    int base = (q >> 11) << 11;            // batch base

    for (int it = 0; it < KNBR; ++it) {
        float best = -3.4e38f; int bj = 0;
        for (int i = tid; i < NN; i += 256) {
            float v = vals[i];
            if (v > best) { best = v; bj = i; }
        }
#pragma unroll
        for (int off = 16; off; off >>= 1) {
            float ov = __shfl_down_sync(0xffffffffu, best, off);
            int   oj = __shfl_down_sync(0xffffffffu, bj, off);
            if (ov > best) { best = ov; bj = oj; }
        }
        if ((tid & 31) == 0) { wv[tid >> 5] = best; wi[tid >> 5] = bj; }
        __syncthreads();
        if (tid == 0) {
            float b2 = wv[0]; int j2 = wi[0];
#pragma unroll
            for (int w = 1; w < 8; ++w)
                if (wv[w] > b2) { b2 = wv[w]; j2 = wi[w]; }
            out[q * KNBR + it] = base + j2;
            vals[j2] = -3.4e38f;
        }
        __syncthreads();
    }
}

// ---------------- weight repack: Wt[2O][C] = [W1-W2 ; W2] ----------------
__global__ void wt_prep(const float* __restrict__ w, float* __restrict__ wt, int C, int O)
{
    int i = blockIdx.x * 256 + threadIdx.x;
    if (i >= 2 * O * C) return;
    int j = i / C, c = i - j * C;
    if (j < O) wt[i] = w[j * 2 * C + c] - w[j * 2 * C + C + c];
    else       wt[i] = w[(j - O) * 2 * C + C + c];
}

// ---------------- BN stats over edges (deterministic partials) ----------------
__global__ void stats_kernel(const float* __restrict__ uv, const int* __restrict__ idx,
                             float* __restrict__ psum, float* __restrict__ psq, int O)
{
    int o = threadIdx.x;
    int twoO = 2 * O;
    __shared__ int sidx[KNBR];
    float s = 0.f, s2 = 0.f;
    int q0 = blockIdx.x * 32;
    for (int q = 0; q < 32; ++q) {
        int n = q0 + q;
        if (o < KNBR) sidx[o] = idx[n * KNBR + o];
        __syncthreads();
        float uo = uv[(size_t)n * twoO + o];
#pragma unroll
        for (int kk = 0; kk < KNBR; ++kk) {
            float h = uo + uv[(size_t)sidx[kk] * twoO + O + o];
            s += h;
            s2 = fmaf(h, h, s2);
        }
        __syncthreads();
    }
    psum[blockIdx.x * O + o] = s;
    psq [blockIdx.x * O + o] = s2;
}

__global__ void finalize_kernel(const float* __restrict__ psum, const float* __restrict__ psq,
                                const float* __restrict__ gamma, const float* __restrict__ beta,
                                float* __restrict__ scale, float* __restrict__ shift,
                                int O, int nblocks)
{
    int o = threadIdx.x;
    float s = 0.f, s2 = 0.f;
    for (int i = 0; i < nblocks; ++i) { s += psum[i * O + o]; s2 += psq[i * O + o]; }
    const float cnt = (float)EDGE_CNT;
    float mean = s / cnt;
    float var  = s2 / cnt - mean * mean;
    float sc = gamma[o] * rsqrtf(var + 1e-5f);
    scale[o] = sc;
    shift[o] = beta[o] - mean * sc;
}

// ---------------- edge max-pool + BN + relu ----------------
__global__ void outmax_kernel(const float* __restrict__ uv, const int* __restrict__ idx,
                              const float* __restrict__ scale, const float* __restrict__ shift,
                              float* __restrict__ xout, int O)
{
    int o = threadIdx.x;
    int twoO = 2 * O;
    __shared__ int sidx[KNBR];
    float sc = scale[o], sh = shift[o];
    int q0 = blockIdx.x * 32;
    for (int q = 0; q < 32; ++q) {
        int n = q0 + q;
        if (o < KNBR) sidx[o] = idx[n * KNBR + o];
        __syncthreads();
        float uo = uv[(size_t)n * twoO + o];
        float mx = -3.4e38f;
#pragma unroll
        for (int kk = 0; kk < KNBR; ++kk) {
            float h = uo + uv[(size_t)sidx[kk] * twoO + O + o];
            float z = fmaf(sc, h, sh);
            mx = fmaxf(mx, z);
        }
        xout[(size_t)n * O + o] = fmaxf(mx, 0.f);
        __syncthreads();
    }
}

// ---------------- global pool + fc ----------------
__global__ void pool_kernel(const float* __restrict__ x3, float* __restrict__ pool)
{
    int b = blockIdx.x, o = threadIdx.x;
    const float* p = x3 + (size_t)b * NN * 256 + o;
    float mx = -3.4e38f;
    for (int n = 0; n < NN; ++n) mx = fmaxf(mx, p[(size_t)n * 256]);
    pool[b * 256 + o] = mx;
}

__global__ void fc_kernel(const float* __restrict__ pool, const float* __restrict__ wo,
                          const float* __restrict__ bo, float* __restrict__ out)
{
    int b = blockIdx.x, j = threadIdx.x;
    __shared__ float ps[256];
    ps[j] = pool[b * 256 + j];
    __syncthreads();
    float s = bo[j];
    for (int o = 0; o < 256; ++o) s = fmaf(ps[o], wo[j * 256 + o], s);
    out[b * 256 + j] = s;
}

// ---------------- host driver ----------------
static void run_layer(const float* xin, int C, int O,
                      const float* w, const float* b, const float* g, const float* be,
                      float* xout,
                      float* D, float* xxp, int* idxp, float* Wt, float* uv,
                      float* psum, float* psq, float* scale, float* shift)
{
    xx_kernel<<<NPTS / 256, 256>>>(xin, xxp, C);

    gemm_nt<1><<<dim3(NN / BN, NN / BM, BB), 256>>>(
        xin, xin, D, NN, NN, C,
        (long long)NN * C, (long long)NN * C, (long long)NN * NN,
        xxp, NN, nullptr, 0);

    topk_kernel<<<NPTS, 256>>>(D, idxp);

    int twoO = 2 * O;
    int total = twoO * C;
    wt_prep<<<(total + 255) / 256, 256>>>(w, Wt, C, O);

    gemm_nt<0><<<dim3(twoO / BN, NPTS / BM, 1), 256>>>(
        xin, Wt, uv, NPTS, twoO, C,
        0, 0, 0, nullptr, 0, b, O);

    stats_kernel<<<512, O>>>(uv, idxp, psum, psq, O);
    finalize_kernel<<<1, O>>>(psum, psq, g, be, scale, shift, O, 512);
    outmax_kernel<<<512, O>>>(uv, idxp, scale, shift, xout, O);
}

extern "C" void kernel_launch(void* const* d_in, const int* in_sizes, int n_in,
                              void* d_out, int out_size)
{
    (void)in_sizes; (void)n_in; (void)out_size;
    const float* x   = (const float*)d_in[0];
    const float* w1  = (const float*)d_in[1];
    const float* b1  = (const float*)d_in[2];
    const float* g1  = (const float*)d_in[3];
    const float* be1 = (const float*)d_in[4];
    const float* w2  = (const float*)d_in[5];
    const float* b2  = (const float*)d_in[6];
    const float* g2  = (const float*)d_in[7];
    const float* be2 = (const float*)d_in[8];
    const float* w3  = (const float*)d_in[9];
    const float* b3  = (const float*)d_in[10];
    const float* g3  = (const float*)d_in[11];
    const float* be3 = (const float*)d_in[12];
    const float* wo  = (const float*)d_in[13];
    const float* bo  = (const float*)d_in[14];

    float *D, *xxp, *Wt, *uv, *xa, *xb, *xc, *psum, *psq, *scale, *shift, *pl;
    int* idxp;
    cudaGetSymbolAddress((void**)&D,     g_D);
    cudaGetSymbolAddress((void**)&idxp,  g_idx);
    cudaGetSymbolAddress((void**)&xxp,   g_xx);
    cudaGetSymbolAddress((void**)&uv,    g_uv);
    cudaGetSymbolAddress((void**)&Wt,    g_Wt);
    cudaGetSymbolAddress((void**)&xa,    g_xa);
    cudaGetSymbolAddress((void**)&xb,    g_xb);
    cudaGetSymbolAddress((void**)&xc,    g_xc);
    cudaGetSymbolAddress((void**)&psum,  g_psum);
    cudaGetSymbolAddress((void**)&psq,   g_psq);
    cudaGetSymbolAddress((void**)&scale, g_scale);
    cudaGetSymbolAddress((void**)&shift, g_shift);
    cudaGetSymbolAddress((void**)&pl,    g_pool);

    run_layer(x,  3,   64,  w1, b1, g1, be1, xa, D, xxp, idxp, Wt, uv, psum, psq, scale, shift);
    run_layer(xa, 64,  128, w2, b2, g2, be2, xb, D, xxp, idxp, Wt, uv, psum, psq, scale, shift);
    run_layer(xb, 128, 256, w3, b3, g3, be3, xc, D, xxp, idxp, Wt, uv, psum, psq, scale, shift);

    pool_kernel<<<BB, 256>>>(xc, pl);
    fc_kernel<<<BB, 256>>>(pl, wo, bo, (float*)d_out);
}

// round 5
// speedup vs baseline: 1.0957x; 1.0957x over previous
#include <cuda_runtime.h>
#include <cuda_bf16.h>
#include <cstdint>

// ---------------- problem constants ----------------
#define BB 8
#define NN 2048
#define KNBR 20
#define NPTS (BB*NN)          // 16384
#define EDGE_CNT (NPTS*KNBR)  // 327680
#define KPMAX 384             // max padded split-K (3*128)

// ---------------- device scratch (static, no runtime alloc) ----------------
__device__ float g_D[(size_t)BB*NN*NN];        // 134 MB pairwise scores
__device__ int   g_idx[NPTS*KNBR];
__device__ float g_xx[NPTS];
__device__ __nv_bfloat16 g_Acat[(size_t)NPTS*KPMAX];  // [hi|hi|lo]
__device__ __nv_bfloat16 g_Bcat[(size_t)NPTS*KPMAX];  // [hi|lo|hi]
__device__ float g_uv[(size_t)NPTS*512];
__device__ float g_Wt[512*128];
__device__ float g_xa[(size_t)NPTS*64];
__device__ float g_xb[(size_t)NPTS*128];
__device__ float g_xc[(size_t)NPTS*256];
__device__ float g_psum[512*256];
__device__ float g_psq [512*256];
__device__ float g_scale[256];
__device__ float g_shift[256];
__device__ float g_pool[BB*256];

// ---------------- hi/lo split pack ----------------
__global__ void prep_cat(const float* __restrict__ x, __nv_bfloat16* __restrict__ Ac,
                         __nv_bfloat16* __restrict__ Bc, int C, int Kp)
{
    long long i = (long long)blockIdx.x * 256 + threadIdx.x;
    long long total = (long long)NPTS * Kp;
    if (i >= total) return;
    int n = (int)(i / Kp);
    int q = (int)(i - (long long)n * Kp);
    __nv_bfloat16 a, b;
    if (q < 3 * C) {
        int seg = q / C, c = q - seg * C;
        float v = x[(size_t)n * C + c];
        __nv_bfloat16 hi = __float2bfloat16(v);
        __nv_bfloat16 lo = __float2bfloat16(v - __bfloat162float(hi));
        if (seg == 0)      { a = hi; b = hi; }
        else if (seg == 1) { a = hi; b = lo; }
        else               { a = lo; b = hi; }
    } else {
        a = __float2bfloat16(0.f); b = a;
    }
    Ac[i] = a; Bc[i] = b;
}

// ---------------- squared norms (exact fp32) ----------------
__global__ void xx_kernel(const float* __restrict__ x, float* __restrict__ xx, int C)
{
    int n = blockIdx.x * 256 + threadIdx.x;
    if (n >= NPTS) return;
    const float* p = x + (size_t)n * C;
    float s = 0.f;
    for (int c = 0; c < C; ++c) s = fmaf(p[c], p[c], s);
    xx[n] = s;
}

// ---------------- HMMA helpers ----------------
__device__ __forceinline__ uint32_t smem_u32(const void* p){
    uint32_t r; asm("{ .reg .u64 t; cvta.to.shared.u64 t, %1; cvt.u32.u64 %0, t; }" : "=r"(r) : "l"(p)); return r;
}
__device__ __forceinline__ void ldm_x4(uint32_t& r0, uint32_t& r1, uint32_t& r2, uint32_t& r3, uint32_t a){
    asm volatile("ldmatrix.sync.aligned.m8n8.x4.shared.b16 {%0,%1,%2,%3}, [%4];"
                 : "=r"(r0), "=r"(r1), "=r"(r2), "=r"(r3) : "r"(a));
}
// B is K-major ([n][k], k contiguous): the m16n8k16 col-major B fragment wants
// two consecutive-k elements at fixed n per thread -> NON-trans ldmatrix.
__device__ __forceinline__ void ldm_x2(uint32_t& r0, uint32_t& r1, uint32_t a){
    asm volatile("ldmatrix.sync.aligned.m8n8.x2.shared.b16 {%0,%1}, [%2];"
                 : "=r"(r0), "=r"(r1) : "r"(a));
}
__device__ __forceinline__ void mma16816(float* c, uint32_t a0, uint32_t a1, uint32_t a2, uint32_t a3,
                                         uint32_t b0, uint32_t b1){
    asm volatile("mma.sync.aligned.m16n8k16.row.col.f32.bf16.bf16.f32 "
                 "{%0,%1,%2,%3}, {%4,%5,%6,%7}, {%8,%9}, {%0,%1,%2,%3};"
                 : "+f"(c[0]), "+f"(c[1]), "+f"(c[2]), "+f"(c[3])
                 : "r"(a0), "r"(a1), "r"(a2), "r"(a3), "r"(b0), "r"(b1));
}
// swizzled smem address: row r, 16B-chunk c (XOR low 3 bits of chunk with row)
__device__ __forceinline__ uint32_t swadr(uint32_t base, int r, int c, int CPR){
    int sc = (c & ~7) | ((c ^ r) & 7);
    return base + (uint32_t)((r * CPR + sc) << 4);
}

// ---------------- HMMA distance GEMM: D = 2*(A·Bᵀ) - xx_col ----------------
// CTA: 128x128 tile, 256 threads = 8 warps (2x4), warp tile 64x32.
__global__ __launch_bounds__(256, 1)
void dist_mma(const __nv_bfloat16* __restrict__ Ac,
              const __nv_bfloat16* __restrict__ Bc,
              const float* __restrict__ xx,
              float* __restrict__ Dout, int Kp)
{
    extern __shared__ char smem[];
    __shared__ float sxx[128];

    const int tid = threadIdx.x, wid = tid >> 5, lane = tid & 31;
    const int colBase = blockIdx.x * 128, rowBase = blockIdx.y * 128, b = blockIdx.z;
    const int CPR = Kp >> 3;                    // 16B chunks per row

    char* smA = smem;
    char* smB = smem + (size_t)256 * Kp;        // 128 rows * Kp * 2B
    const uint32_t uA = smem_u32(smA), uB = smem_u32(smB);

    if (tid < 128) sxx[tid] = xx[b * NN + colBase + tid];

    // cooperative swizzled tile load
    const __nv_bfloat16* gA = Ac + (size_t)(b * NN + rowBase) * Kp;
    const __nv_bfloat16* gB = Bc + (size_t)(b * NN + colBase) * Kp;
    int nchunks = 128 * CPR;
    for (int i = tid; i < nchunks; i += 256) {
        int r = i / CPR, c = i - r * CPR;
        uint32_t off = (uint32_t)((r * CPR + ((c & ~7) | ((c ^ r) & 7))) << 4);
        uint4 va = *reinterpret_cast<const uint4*>(gA + (size_t)r * Kp + c * 8);
        uint4 vb = *reinterpret_cast<const uint4*>(gB + (size_t)r * Kp + c * 8);
        *reinterpret_cast<uint4*>(smA + off) = va;
        *reinterpret_cast<uint4*>(smB + off) = vb;
    }
    __syncthreads();

    // warp layout: 2 (m) x 4 (n); warp tile 64 x 32
    const int wm = wid & 1, wn = wid >> 1;
    const int mW = wm * 64, nW = wn * 32;

    float acc[4][4][4];
#pragma unroll
    for (int i = 0; i < 4; ++i)
#pragma unroll
        for (int j = 0; j < 4; ++j)
#pragma unroll
            for (int q = 0; q < 4; ++q) acc[i][j][q] = 0.f;

    const int aRow = lane & 15, aCH = lane >> 4;       // ldmatrix x4 addressing
    const int bRow = lane & 7,  bCH = (lane >> 3) & 1; // ldmatrix x2 addressing

    for (int k0 = 0; k0 < Kp; k0 += 16) {
        int cbase = k0 >> 3;
        uint32_t a0[4], a1[4], a2[4], a3[4];
#pragma unroll
        for (int mi = 0; mi < 4; ++mi) {
            int r = mW + mi * 16 + aRow;
            ldm_x4(a0[mi], a1[mi], a2[mi], a3[mi], swadr(uA, r, cbase + aCH, CPR));
        }
        uint32_t b0[4], b1[4];
#pragma unroll
        for (int ni = 0; ni < 4; ++ni) {
            int r = nW + ni * 8 + bRow;
            ldm_x2(b0[ni], b1[ni], swadr(uB, r, cbase + bCH, CPR));
        }
#pragma unroll
        for (int mi = 0; mi < 4; ++mi)
#pragma unroll
            for (int ni = 0; ni < 4; ++ni)
                mma16816(acc[mi][ni], a0[mi], a1[mi], a2[mi], a3[mi], b0[ni], b1[ni]);
    }
    __syncthreads();   // done reading operands; reuse smem for C staging

    // stage C tile in smem (fp32, padded stride)
    float* Cs = reinterpret_cast<float*>(smem);
    const int CSTR = 132;
    {
        int tq = lane >> 2, tr = lane & 3;
#pragma unroll
        for (int mi = 0; mi < 4; ++mi) {
#pragma unroll
            for (int ni = 0; ni < 4; ++ni) {
                int row0 = mW + mi * 16 + tq;
                int col  = nW + ni * 8 + tr * 2;
                Cs[row0 * CSTR + col]       = acc[mi][ni][0];
                Cs[row0 * CSTR + col + 1]   = acc[mi][ni][1];
                Cs[(row0 + 8) * CSTR + col]     = acc[mi][ni][2];
                Cs[(row0 + 8) * CSTR + col + 1] = acc[mi][ni][3];
            }
        }
    }
    __syncthreads();

    // coalesced epilogue: D = 2*acc - xx[col]
    float* Db = Dout + (size_t)b * NN * NN;
    for (int i = tid; i < 128 * 32; i += 256) {
        int r = i >> 5, c4 = (i & 31) << 2;
        const float* src = Cs + r * CSTR + c4;
        float4 v;
        v.x = 2.f * src[0] - sxx[c4 + 0];
        v.y = 2.f * src[1] - sxx[c4 + 1];
        v.z = 2.f * src[2] - sxx[c4 + 2];
        v.w = 2.f * src[3] - sxx[c4 + 3];
        *reinterpret_cast<float4*>(Db + (size_t)(rowBase + r) * NN + colBase + c4) = v;
    }
}

// ---------------- fp32 GEMM-NT for u|v ----------------
#define BM 128
#define BN 128
#define BKK 16

__global__ void gemm_uv(const float* __restrict__ A, const float* __restrict__ Bm,
                        float* __restrict__ Cout, int M, int Nn, int K,
                        const float* __restrict__ bias, int Obias)
{
    __shared__ float As[BKK][BM + 4];
    __shared__ float Bs[BKK][BN + 4];

    int tid = threadIdx.x;
    int tx = tid & 15, ty = tid >> 4;
    int tx4 = tx * 4, ty4 = ty * 4;
    int rowBase = blockIdx.y * BM;
    int colBase = blockIdx.x * BN;

    float acc[8][8];
#pragma unroll
    for (int i = 0; i < 8; ++i)
#pragma unroll
        for (int j = 0; j < 8; ++j) acc[i][j] = 0.f;

    for (int k0 = 0; k0 < K; k0 += BKK) {
#pragma unroll
        for (int i = 0; i < 8; ++i) {
            int idx = tid + i * 256;
            int kk = idx & 15, r = idx >> 4;
            int gk = k0 + kk;
            As[kk][r] = (gk < K) ? A[(size_t)(rowBase + r) * K + gk] : 0.f;
        }
#pragma unroll
        for (int i = 0; i < 8; ++i) {
            int idx = tid + i * 256;
            int kk = idx & 15, r = idx >> 4;
            int gk = k0 + kk;
            Bs[kk][r] = (gk < K) ? Bm[(size_t)(colBase + r) * K + gk] : 0.f;
        }
        __syncthreads();

#pragma unroll
        for (int kk = 0; kk < BKK; ++kk) {
            float4 a0 = *reinterpret_cast<const float4*>(&As[kk][ty4]);
            float4 a1 = *reinterpret_cast<const float4*>(&As[kk][ty4 + 64]);
            float4 b0 = *reinterpret_cast<const float4*>(&Bs[kk][tx4]);
            float4 b1 = *reinterpret_cast<const float4*>(&Bs[kk][tx4 + 64]);
            float av[8] = {a0.x, a0.y, a0.z, a0.w, a1.x, a1.y, a1.z, a1.w};
            float bv[8] = {b0.x, b0.y, b0.z, b0.w, b1.x, b1.y, b1.z, b1.w};
#pragma unroll
            for (int i = 0; i < 8; ++i)
#pragma unroll
                for (int j = 0; j < 8; ++j)
                    acc[i][j] = fmaf(av[i], bv[j], acc[i][j]);
        }
        __syncthreads();
    }

    float colv[8];
#pragma unroll
    for (int j = 0; j < 8; ++j) {
        int c = colBase + ((j < 4) ? tx4 + j : tx4 + j + 60);
        colv[j] = (c < Obias) ? bias[c] : 0.f;
    }
#pragma unroll
    for (int i = 0; i < 8; ++i) {
        int r = rowBase + ((i < 4) ? ty4 + i : ty4 + i + 60);
        float out[8];
#pragma unroll
        for (int j = 0; j < 8; ++j) out[j] = acc[i][j] + colv[j];
        float4 v0 = make_float4(out[0], out[1], out[2], out[3]);
        float4 v1 = make_float4(out[4], out[5], out[6], out[7]);
        *reinterpret_cast<float4*>(&Cout[(size_t)r * Nn + colBase + tx4])      = v0;
        *reinterpret_cast<float4*>(&Cout[(size_t)r * Nn + colBase + tx4 + 64]) = v1;
    }
}

// ---------------- top-k per query ----------------
__global__ void topk_kernel(const float* __restrict__ D, int* __restrict__ out)
{
    __shared__ float vals[NN];
    __shared__ float wv[8];
    __shared__ int   wi[8];

    int q = blockIdx.x;
    const float* row = D + (size_t)q * NN;
    int tid = threadIdx.x;

    for (int i = tid; i < NN; i += 256) vals[i] = row[i];
    __syncthreads();

    int base = (q >> 11) << 11;

    for (int it = 0; it < KNBR; ++it) {
        float best = -3.4e38f; int bj = 0;
        for (int i = tid; i < NN; i += 256) {
            float v = vals[i];
            if (v > best) { best = v; bj = i; }
        }
#pragma unroll
        for (int off = 16; off; off >>= 1) {
            float ov = __shfl_down_sync(0xffffffffu, best, off);
            int   oj = __shfl_down_sync(0xffffffffu, bj, off);
            if (ov > best) { best = ov; bj = oj; }
        }
        if ((tid & 31) == 0) { wv[tid >> 5] = best; wi[tid >> 5] = bj; }
        __syncthreads();
        if (tid == 0) {
            float b2 = wv[0]; int j2 = wi[0];
#pragma unroll
            for (int w = 1; w < 8; ++w)
                if (wv[w] > b2) { b2 = wv[w]; j2 = wi[w]; }
            out[q * KNBR + it] = base + j2;
            vals[j2] = -3.4e38f;
        }
        __syncthreads();
    }
}

// ---------------- weight repack: Wt[2O][C] = [W1-W2 ; W2] ----------------
__global__ void wt_prep(const float* __restrict__ w, float* __restrict__ wt, int C, int O)
{
    int i = blockIdx.x * 256 + threadIdx.x;
    if (i >= 2 * O * C) return;
    int j = i / C, c = i - j * C;
    if (j < O) wt[i] = w[j * 2 * C + c] - w[j * 2 * C + C + c];
    else       wt[i] = w[(j - O) * 2 * C + C + c];
}

// ---------------- BN stats over edges ----------------
__global__ void stats_kernel(const float* __restrict__ uv, const int* __restrict__ idx,
                             float* __restrict__ psum, float* __restrict__ psq, int O)
{
    int o = threadIdx.x;
    int twoO = 2 * O;
    __shared__ int sidx[KNBR];
    float s = 0.f, s2 = 0.f;
    int q0 = blockIdx.x * 32;
    for (int q = 0; q < 32; ++q) {
        int n = q0 + q;
        if (o < KNBR) sidx[o] = idx[n * KNBR + o];
        __syncthreads();
        float uo = uv[(size_t)n * twoO + o];
#pragma unroll
        for (int kk = 0; kk < KNBR; ++kk) {
            float h = uo + uv[(size_t)sidx[kk] * twoO + O + o];
            s += h;
            s2 = fmaf(h, h, s2);
        }
        __syncthreads();
    }
    psum[blockIdx.x * O + o] = s;
    psq [blockIdx.x * O + o] = s2;
}

__global__ void finalize_kernel(const float* __restrict__ psum, const float* __restrict__ psq,
                                const float* __restrict__ gamma, const float* __restrict__ beta,
                                float* __restrict__ scale, float* __restrict__ shift,
                                int O, int nblocks)
{
    int o = threadIdx.x;
    float s = 0.f, s2 = 0.f;
    for (int i = 0; i < nblocks; ++i) { s += psum[i * O + o]; s2 += psq[i * O + o]; }
    const float cnt = (float)EDGE_CNT;
    float mean = s / cnt;
    float var  = s2 / cnt - mean * mean;
    float sc = gamma[o] * rsqrtf(var + 1e-5f);
    scale[o] = sc;
    shift[o] = beta[o] - mean * sc;
}

// ---------------- edge max-pool + BN + relu ----------------
__global__ void outmax_kernel(const float* __restrict__ uv, const int* __restrict__ idx,
                              const float* __restrict__ scale, const float* __restrict__ shift,
                              float* __restrict__ xout, int O)
{
    int o = threadIdx.x;
    int twoO = 2 * O;
    __shared__ int sidx[KNBR];
    float sc = scale[o], sh = shift[o];
    int q0 = blockIdx.x * 32;
    for (int q = 0; q < 32; ++q) {
        int n = q0 + q;
        if (o < KNBR) sidx[o] = idx[n * KNBR + o];
        __syncthreads();
        float uo = uv[(size_t)n * twoO + o];
        float mx = -3.4e38f;
#pragma unroll
        for (int kk = 0; kk < KNBR; ++kk) {
            float h = uo + uv[(size_t)sidx[kk] * twoO + O + o];
            float z = fmaf(sc, h, sh);
            mx = fmaxf(mx, z);
        }
        xout[(size_t)n * O + o] = fmaxf(mx, 0.f);
        __syncthreads();
    }
}

// ---------------- global pool + fc ----------------
__global__ void pool_kernel(const float* __restrict__ x3, float* __restrict__ pool)
{
    int b = blockIdx.x, o = threadIdx.x;
    const float* p = x3 + (size_t)b * NN * 256 + o;
    float mx = -3.4e38f;
    for (int n = 0; n < NN; ++n) mx = fmaxf(mx, p[(size_t)n * 256]);
    pool[b * 256 + o] = mx;
}

__global__ void fc_kernel(const float* __restrict__ pool, const float* __restrict__ wo,
                          const float* __restrict__ bo, float* __restrict__ out)
{
    int b = blockIdx.x, j = threadIdx.x;
    __shared__ float ps[256];
    ps[j] = pool[b * 256 + j];
    __syncthreads();
    float s = bo[j];
    for (int o = 0; o < 256; ++o) s = fmaf(ps[o], wo[j * 256 + o], s);
    out[b * 256 + j] = s;
}

// ---------------- host driver ----------------
static void run_layer(const float* xin, int C, int O,
                      const float* w, const float* b, const float* g, const float* be,
                      float* xout,
                      float* D, float* xxp, int* idxp, float* Wt, float* uv,
                      __nv_bfloat16* Ac, __nv_bfloat16* Bc,
                      float* psum, float* psq, float* scale, float* shift)
{
    int twoO = 2 * O;
    int total = twoO * C;
    wt_prep<<<(total + 255) / 256, 256>>>(w, Wt, C, O);

    int Kp = (3 * C + 63) & ~63;
    long long cat_total = (long long)NPTS * Kp;
    prep_cat<<<(unsigned)((cat_total + 255) / 256), 256>>>(xin, Ac, Bc, C, Kp);
    xx_kernel<<<NPTS / 256, 256>>>(xin, xxp, C);

    size_t smem_bytes = (size_t)512 * Kp;                   // A+B tiles
    size_t cs_bytes = 128 * 132 * sizeof(float);            // C staging
    if (cs_bytes > smem_bytes) smem_bytes = cs_bytes;
    dist_mma<<<dim3(16, 16, BB), 256, smem_bytes>>>(Ac, Bc, xxp, D, Kp);

    topk_kernel<<<NPTS, 256>>>(D, idxp);

    gemm_uv<<<dim3(twoO / BN, NPTS / BM), 256>>>(xin, Wt, uv, NPTS, twoO, C, b, O);

    stats_kernel<<<512, O>>>(uv, idxp, psum, psq, O);
    finalize_kernel<<<1, O>>>(psum, psq, g, be, scale, shift, O, 512);
    outmax_kernel<<<512, O>>>(uv, idxp, scale, shift, xout, O);
}

extern "C" void kernel_launch(void* const* d_in, const int* in_sizes, int n_in,
                              void* d_out, int out_size)
{
    (void)in_sizes; (void)n_in; (void)out_size;
    const float* x   = (const float*)d_in[0];
    const float* w1  = (const float*)d_in[1];
    const float* b1  = (const float*)d_in[2];
    const float* g1  = (const float*)d_in[3];
    const float* be1 = (const float*)d_in[4];
    const float* w2  = (const float*)d_in[5];
    const float* b2  = (const float*)d_in[6];
    const float* g2  = (const float*)d_in[7];
    const float* be2 = (const float*)d_in[8];
    const float* w3  = (const float*)d_in[9];
    const float* b3  = (const float*)d_in[10];
    const float* g3  = (const float*)d_in[11];
    const float* be3 = (const float*)d_in[12];
    const float* wo  = (const float*)d_in[13];
    const float* bo  = (const float*)d_in[14];

    cudaFuncSetAttribute(dist_mma, cudaFuncAttributeMaxDynamicSharedMemorySize,
                         512 * KPMAX);

    float *D, *xxp, *Wt, *uv, *xa, *xb, *xc, *psum, *psq, *scale, *shift, *pl;
    __nv_bfloat16 *Ac, *Bc;
    int* idxp;
    cudaGetSymbolAddress((void**)&D,     g_D);
    cudaGetSymbolAddress((void**)&idxp,  g_idx);
    cudaGetSymbolAddress((void**)&xxp,   g_xx);
    cudaGetSymbolAddress((void**)&uv,    g_uv);
    cudaGetSymbolAddress((void**)&Wt,    g_Wt);
    cudaGetSymbolAddress((void**)&xa,    g_xa);
    cudaGetSymbolAddress((void**)&xb,    g_xb);
    cudaGetSymbolAddress((void**)&xc,    g_xc);
    cudaGetSymbolAddress((void**)&psum,  g_psum);
    cudaGetSymbolAddress((void**)&psq,   g_psq);
    cudaGetSymbolAddress((void**)&scale, g_scale);
    cudaGetSymbolAddress((void**)&shift, g_shift);
    cudaGetSymbolAddress((void**)&pl,    g_pool);
    cudaGetSymbolAddress((void**)&Ac,    g_Acat);
    cudaGetSymbolAddress((void**)&Bc,    g_Bcat);

    run_layer(x,  3,   64,  w1, b1, g1, be1, xa, D, xxp, idxp, Wt, uv, Ac, Bc, psum, psq, scale, shift);
    run_layer(xa, 64,  128, w2, b2, g2, be2, xb, D, xxp, idxp, Wt, uv, Ac, Bc, psum, psq, scale, shift);
    run_layer(xb, 128, 256, w3, b3, g3, be3, xc, D, xxp, idxp, Wt, uv, Ac, Bc, psum, psq, scale, shift);

    pool_kernel<<<BB, 256>>>(xc, pl);
    fc_kernel<<<BB, 256>>>(pl, wo, bo, (float*)d_out);
}